// round 3
// baseline (speedup 1.0000x reference)
#include <cuda_runtime.h>

// ============================================================================
// Soft K-means (transductive) — fused per-iteration kernel for GB300 sm_103a.
//
// Shapes (fixed by the problem): Nq = 2^21, d = 64, C = 16, Nsup = 512,
// n_iter = 50, beta = 5.
//
// Key identities:
//   softmax(-beta*d2) with d2 = q_sq - 2 q.c + |c|^2 is invariant to the
//   per-row constant q_sq, so we only need  logit = 2*beta*(q.c) - beta*|c|^2.
//   argmin d2 == argmax logit (beta > 0), ties -> lower class index.
//
// Layout: each warp = 16 classes x 2 dim-halves. Lane (c,h) owns class c and
// the float4 chunks {2k+h} of every query row (dims 8k+4h .. 8k+4h+3).
// Per query: 8 LDS.128 + 16 FFMA2 (dot) + warp softmax + 16 FFMA2 (accum into
// per-lane register accumulators). Accumulators flush once per block into a
// deterministic per-block partial buffer; a 16-block reducer forms the new
// centroids. No float atomics anywhere -> bitwise deterministic.
// ============================================================================

#define NQ        (1 << 21)
#define DIM       64
#define NCLS      16
#define NSUP      512
#define NITER     50
#define BETA_F    5.0f
#define TILE_Q    64
#define NTILES    (NQ / TILE_Q)        // 32768
#define GRID_MAIN 296                  // 2 blocks / SM * 148 SMs
#define TPB       256
#define NWARPS    (TPB / 32)
#define QPW       (TILE_Q / NWARPS)    // 8 queries per warp per tile

// ---------------- device scratch (static: no allocations allowed) -----------
__device__ float  g_sup_sum[NCLS][DIM];
__device__ float  g_counts[NCLS];
__device__ float  g_cs[NCLS][DIM];                 // 2*beta*centroid
__device__ float  g_bias[NCLS];                    // beta*|centroid|^2
__device__ float2 g_part[GRID_MAIN][32][16];       // per-block partial sums
__device__ float  g_pden[GRID_MAIN][NCLS];         // per-block weight sums
__device__ int    g_match;
__device__ int    g_lab64;                         // labels stored as int64?

// ---------------- helpers ---------------------------------------------------
__device__ __forceinline__ float2 ffma2(const float2 a, const float2 b,
                                        const float2 c) {
    // packed f32x2 FMA (FFMA2) — only reachable via PTX on sm_103a
    float2 r;
    asm("{\n\t"
        ".reg .b64 ra, rb, rc;\n\t"
        "mov.b64 ra, {%2, %3};\n\t"
        "mov.b64 rb, {%4, %5};\n\t"
        "mov.b64 rc, {%6, %7};\n\t"
        "fma.rn.f32x2 rc, ra, rb, rc;\n\t"
        "mov.b64 {%0, %1}, rc;\n\t"
        "}"
        : "=f"(r.x), "=f"(r.y)
        : "f"(a.x), "f"(a.y), "f"(b.x), "f"(b.y), "f"(c.x), "f"(c.y));
    return r;
}

__device__ __forceinline__ void cp16(void* smem_dst, const void* gsrc) {
    unsigned s = (unsigned)__cvta_generic_to_shared(smem_dst);
    asm volatile("cp.async.cg.shared.global [%0], [%1], 16;\n"
                 :: "r"(s), "l"(gsrc));
}
#define CP_COMMIT() asm volatile("cp.async.commit_group;\n" ::: "memory")
#define CP_WAIT1()  asm volatile("cp.async.wait_group 1;\n" ::: "memory")

__device__ __forceinline__ void stage_tile(float* dst, const float* __restrict__ qf,
                                           int tile, int tid) {
    const float4* src = (const float4*)(qf + (size_t)tile * (TILE_Q * DIM));
    float4* d4 = (float4*)dst;
#pragma unroll
    for (int k = 0; k < 4; k++)                      // 1024 float4 per tile
        cp16(&d4[k * TPB + tid], &src[k * TPB + tid]);
}

// ---------------- init: support sums + initial centroids + dtype detect -----
__global__ void init_kernel(const float* __restrict__ sup, const void* slab) {
    __shared__ int s64;
    if (threadIdx.x == 0) {
        // support_labels = arange(512) % 16. If stored as int32, the int64
        // view of words 1..3 has nonzero high halves (1,3,...); if int64,
        // all high halves are 0. Unambiguous.
        const unsigned long long* p = (const unsigned long long*)slab;
        int is64 = 1;
#pragma unroll
        for (int i = 0; i < 4; i++)
            if ((p[i] >> 32) != 0ull) is64 = 0;
        s64 = is64;
        g_lab64 = is64;
        g_match = 0;
    }
    __syncthreads();
    const int is64 = s64;
    const int c = threadIdx.x >> 5;      // warp == class (512 threads)
    const int j = threadIdx.x & 31;      // dim pair
    const long long* l64 = (const long long*)slab;
    const int*       l32 = (const int*)slab;

    float sx = 0.f, sy = 0.f;
    int cnt = 0;
    for (int s = 0; s < NSUP; s++) {
        int lbl = is64 ? (int)l64[s] : l32[s];
        if (lbl == c) {
            float2 v = ((const float2*)(sup + s * DIM))[j];
            sx += v.x; sy += v.y; cnt++;
        }
    }
    g_sup_sum[c][2 * j]     = sx;
    g_sup_sum[c][2 * j + 1] = sy;
    float inv = 1.0f / (float)cnt;
    float c0 = sx * inv, c1 = sy * inv;
    g_cs[c][2 * j]     = 2.0f * BETA_F * c0;
    g_cs[c][2 * j + 1] = 2.0f * BETA_F * c1;
    float sq = c0 * c0 + c1 * c1;
#pragma unroll
    for (int m = 16; m > 0; m >>= 1)
        sq += __shfl_xor_sync(0xffffffffu, sq, m);
    if (j == 0) {
        g_counts[c] = (float)cnt;
        g_bias[c]   = BETA_F * sq;
    }
}

// ---------------- fused iteration kernel ------------------------------------
__global__ void __launch_bounds__(TPB, 2)
iter_kernel(const float* __restrict__ qf) {
    __shared__ alignas(16) float sbuf[2][TILE_Q * DIM];  // 2 x 16 KB
    __shared__ float2 sacc[32][17];                      // padded vs conflicts
    __shared__ float  sden[32];

    const int tid  = threadIdx.x;
    const int wid  = tid >> 5;
    const int lane = tid & 31;
    const int c    = lane & 15;
    const int h    = lane >> 4;

    // class parameters (2*beta*c), chunks {2k+h} of the class row
    float4 cs[8];
    const float4* csrow = (const float4*)g_cs[c];
#pragma unroll
    for (int k = 0; k < 8; k++) cs[k] = csrow[2 * k + h];
    const float bias = g_bias[c];

    float2 acc[16];
#pragma unroll
    for (int i = 0; i < 16; i++) { acc[i].x = 0.f; acc[i].y = 0.f; }
    float wsum = 0.f;

    int t = blockIdx.x;
    if (t < NTILES) stage_tile(sbuf[0], qf, t, tid);
    CP_COMMIT();
    int buf = 0;

    for (; t < NTILES; t += gridDim.x) {
        int tn = t + gridDim.x;
        if (tn < NTILES) stage_tile(sbuf[buf ^ 1], qf, tn, tid);
        CP_COMMIT();
        CP_WAIT1();
        __syncthreads();

        const float* base = sbuf[buf] + wid * (QPW * DIM);
#pragma unroll 2
        for (int qi = 0; qi < QPW; qi++) {
            const float4* qrow = (const float4*)(base + qi * DIM);
            float2 dA = {0.f, 0.f}, dB = {0.f, 0.f};
#pragma unroll
            for (int k = 0; k < 8; k++) {
                float4 qv = qrow[2 * k + h];
                float2 q01 = {qv.x, qv.y}, q23 = {qv.z, qv.w};
                float2 c01 = {cs[k].x, cs[k].y}, c23 = {cs[k].z, cs[k].w};
                dA = ffma2(q01, c01, dA);
                dB = ffma2(q23, c23, dB);
            }
            float dot = (dA.x + dA.y) + (dB.x + dB.y);
            dot += __shfl_xor_sync(0xffffffffu, dot, 16);  // combine halves
            float logit = dot - bias;                       // beta*(2qc-|c|^2)

            float m = logit;                                // softmax, 16 lanes
#pragma unroll
            for (int msk = 8; msk >= 1; msk >>= 1)
                m = fmaxf(m, __shfl_xor_sync(0xffffffffu, m, msk));
            float e = __expf(logit - m);
            float ssum = e;
#pragma unroll
            for (int msk = 8; msk >= 1; msk >>= 1)
                ssum += __shfl_xor_sync(0xffffffffu, ssum, msk);
            float w = __fdividef(e, ssum);
            wsum += w;

            float2 wp = {w, w};
#pragma unroll
            for (int k = 0; k < 8; k++) {
                float4 qv = qrow[2 * k + h];
                float2 q01 = {qv.x, qv.y}, q23 = {qv.z, qv.w};
                acc[2 * k]     = ffma2(wp, q01, acc[2 * k]);
                acc[2 * k + 1] = ffma2(wp, q23, acc[2 * k + 1]);
            }
        }
        buf ^= 1;
        __syncthreads();
    }

    // deterministic block flush: serialize warps into smem, then write partials
    for (int ws = 0; ws < NWARPS; ws++) {
        if (wid == ws) {
            if (ws == 0) {
#pragma unroll
                for (int i = 0; i < 16; i++) sacc[lane][i] = acc[i];
                sden[lane] = wsum;
            } else {
#pragma unroll
                for (int i = 0; i < 16; i++) {
                    sacc[lane][i].x += acc[i].x;
                    sacc[lane][i].y += acc[i].y;
                }
                sden[lane] += wsum;
            }
        }
        __syncthreads();
    }
    if (wid == 0) {
#pragma unroll
        for (int i = 0; i < 16; i++)
            g_part[blockIdx.x][lane][i] = sacc[lane][i];
    }
    if (wid == 1 && lane < 16)
        g_pden[blockIdx.x][lane] = sden[lane];   // both halves equal; h=0 copy
}

// ---------------- centroid update (16 blocks, deterministic) ----------------
__global__ void reduce_kernel() {
    __shared__ float2 red[8][32];
    __shared__ float  dch[8];
    __shared__ float  sqv[32];
    __shared__ float  den_s;

    const int c     = blockIdx.x;       // class
    const int tid   = threadIdx.x;      // 256 threads
    const int s     = tid & 31;         // slot: h = s>>4, i = s&15
    const int chunk = tid >> 5;         // 8 chunks over GRID_MAIN blocks
    const int hh    = s >> 4;
    const int ii    = s & 15;
    const int l     = c + 16 * hh;
    const int per   = GRID_MAIN / 8;    // 37

    float2 t2 = {0.f, 0.f};
    float dsum = 0.f;
    const int b0 = chunk * per;
    for (int b = b0; b < b0 + per; b++) {
        float2 v = g_part[b][l][ii];
        t2.x += v.x; t2.y += v.y;
        if (s == 0) dsum += g_pden[b][c];
    }
    red[chunk][s] = t2;
    if (s == 0) dch[chunk] = dsum;
    __syncthreads();

    if (tid == 0) {
        float dtot = g_counts[c];
        for (int k = 0; k < 8; k++) dtot += dch[k];
        den_s = dtot;
    }
    __syncthreads();

    if (tid < 32) {
        float2 tot = red[0][tid];
#pragma unroll
        for (int k = 1; k < 8; k++) {
            tot.x += red[k][tid].x;
            tot.y += red[k][tid].y;
        }
        const int h2 = tid >> 4, i2 = tid & 15;
        const int k2 = i2 >> 1, r2 = i2 & 1;
        const int d0 = 8 * k2 + 4 * h2 + 2 * r2;   // matches iter acc layout
        float num0 = g_sup_sum[c][d0]     + tot.x;
        float num1 = g_sup_sum[c][d0 + 1] + tot.y;
        float c0 = num0 / den_s;
        float c1 = num1 / den_s;
        g_cs[c][d0]     = 2.0f * BETA_F * c0;
        g_cs[c][d0 + 1] = 2.0f * BETA_F * c1;
        sqv[tid] = c0 * c0 + c1 * c1;
    }
    __syncthreads();
    if (tid == 0) {
        float sq = 0.f;
        for (int k = 0; k < 32; k++) sq += sqv[k];
        g_bias[c] = BETA_F * sq;
    }
}

// ---------------- final prediction + accuracy count -------------------------
__global__ void __launch_bounds__(TPB, 2)
predict_kernel(const float* __restrict__ qf, const void* __restrict__ qlab) {
    __shared__ alignas(16) float sbuf[2][TILE_Q * DIM];
    __shared__ int scnt[NWARPS];

    const int tid  = threadIdx.x;
    const int wid  = tid >> 5;
    const int lane = tid & 31;
    const int c    = lane & 15;
    const int h    = lane >> 4;

    float4 cs[8];
    const float4* csrow = (const float4*)g_cs[c];
#pragma unroll
    for (int k = 0; k < 8; k++) cs[k] = csrow[2 * k + h];
    const float bias = g_bias[c];

    const int is64 = g_lab64;
    const long long* L64 = (const long long*)qlab;
    const int*       L32 = (const int*)qlab;

    int cnt = 0;
    int t = blockIdx.x;
    if (t < NTILES) stage_tile(sbuf[0], qf, t, tid);
    CP_COMMIT();
    int buf = 0;

    for (; t < NTILES; t += gridDim.x) {
        int tn = t + gridDim.x;
        if (tn < NTILES) stage_tile(sbuf[buf ^ 1], qf, tn, tid);
        CP_COMMIT();
        CP_WAIT1();
        __syncthreads();

        const float* base = sbuf[buf] + wid * (QPW * DIM);
#pragma unroll 2
        for (int qi = 0; qi < QPW; qi++) {
            const float4* qrow = (const float4*)(base + qi * DIM);
            float2 dA = {0.f, 0.f}, dB = {0.f, 0.f};
#pragma unroll
            for (int k = 0; k < 8; k++) {
                float4 qv = qrow[2 * k + h];
                float2 q01 = {qv.x, qv.y}, q23 = {qv.z, qv.w};
                float2 c01 = {cs[k].x, cs[k].y}, c23 = {cs[k].z, cs[k].w};
                dA = ffma2(q01, c01, dA);
                dB = ffma2(q23, c23, dB);
            }
            float dot = (dA.x + dA.y) + (dB.x + dB.y);
            dot += __shfl_xor_sync(0xffffffffu, dot, 16);
            float v = dot - bias;          // argmax v == argmin d2
            int bi = c;
#pragma unroll
            for (int msk = 8; msk >= 1; msk >>= 1) {
                float ov = __shfl_xor_sync(0xffffffffu, v, msk);
                int   oi = __shfl_xor_sync(0xffffffffu, bi, msk);
                if (ov > v || (ov == v && oi < bi)) { v = ov; bi = oi; }
            }
            if (lane == 0) {
                int qg = t * TILE_Q + wid * QPW + qi;
                int lbl = is64 ? (int)L64[qg] : L32[qg];
                if (bi == lbl) cnt++;
            }
        }
        buf ^= 1;
        __syncthreads();
    }

    if (lane == 0) scnt[wid] = cnt;
    __syncthreads();
    if (tid == 0) {
        int bc = 0;
#pragma unroll
        for (int w = 0; w < NWARPS; w++) bc += scnt[w];
        atomicAdd(&g_match, bc);           // integer atomic: deterministic
    }
}

__global__ void finalize_kernel(float* out) {
    out[0] = (float)g_match / (float)NQ;
}

// ---------------- launch ----------------------------------------------------
extern "C" void kernel_launch(void* const* d_in, const int* in_sizes, int n_in,
                              void* d_out, int out_size) {
    (void)in_sizes; (void)n_in; (void)out_size;
    const float* sup  = (const float*)d_in[0];
    const float* qf   = (const float*)d_in[1];
    const void*  slab = d_in[2];
    const void*  qlab = d_in[3];
    float* out = (float*)d_out;

    init_kernel<<<1, 512>>>(sup, slab);
    for (int it = 0; it < NITER; ++it) {
        iter_kernel<<<GRID_MAIN, TPB>>>(qf);
        reduce_kernel<<<NCLS, 256>>>();
    }
    predict_kernel<<<GRID_MAIN, TPB>>>(qf, qlab);
    finalize_kernel<<<1, 1>>>(out);
}

// round 4
// speedup vs baseline: 1.7491x; 1.7491x over previous
#include <cuda_runtime.h>

// ============================================================================
// Soft K-means (transductive) — fused per-iteration kernel for GB300 sm_103a.
// R3: 3-phase (dot / softmax / accumulate) structure, fully unrolled over the
// 8 queries a warp owns per tile, so the 9-deep shuffle+MUFU softmax chains
// issue 8-wide instead of serially. Everything else identical to the passing
// R2 kernel (bitwise-compatible math per query).
//
// Shapes (fixed): Nq = 2^21, d = 64, C = 16, Nsup = 512, n_iter = 50, beta = 5.
//
// Identity: softmax(-beta*d2) is invariant to the per-row q_sq term, so
// logit = 2*beta*(q.c) - beta*|c|^2 suffices; argmin d2 == argmax logit.
//
// Warp layout: lane (c,h) = 16 classes x 2 dim-halves. Lane owns float4
// chunks {2k+h} (dims 8k+4h..8k+4h+3) of every query row and class row.
// ============================================================================

#define NQ        (1 << 21)
#define DIM       64
#define NCLS      16
#define NSUP      512
#define NITER     50
#define BETA_F    5.0f
#define TILE_Q    64
#define NTILES    (NQ / TILE_Q)        // 32768
#define GRID_MAIN 296                  // 2 blocks / SM * 148 SMs
#define TPB       256
#define NWARPS    (TPB / 32)
#define QPW       (TILE_Q / NWARPS)    // 8 queries per warp per tile

// ---------------- device scratch (static: no allocations allowed) -----------
__device__ float  g_sup_sum[NCLS][DIM];
__device__ float  g_counts[NCLS];
__device__ float  g_cs[NCLS][DIM];                 // 2*beta*centroid
__device__ float  g_bias[NCLS];                    // beta*|centroid|^2
__device__ float2 g_part[GRID_MAIN][32][16];       // per-block partial sums
__device__ float  g_pden[GRID_MAIN][NCLS];         // per-block weight sums
__device__ int    g_match;
__device__ int    g_lab64;                         // labels stored as int64?

// ---------------- helpers ---------------------------------------------------
__device__ __forceinline__ float2 ffma2(const float2 a, const float2 b,
                                        const float2 c) {
    // packed f32x2 FMA (FFMA2) — only reachable via PTX on sm_103a
    float2 r;
    asm("{\n\t"
        ".reg .b64 ra, rb, rc;\n\t"
        "mov.b64 ra, {%2, %3};\n\t"
        "mov.b64 rb, {%4, %5};\n\t"
        "mov.b64 rc, {%6, %7};\n\t"
        "fma.rn.f32x2 rc, ra, rb, rc;\n\t"
        "mov.b64 {%0, %1}, rc;\n\t"
        "}"
        : "=f"(r.x), "=f"(r.y)
        : "f"(a.x), "f"(a.y), "f"(b.x), "f"(b.y), "f"(c.x), "f"(c.y));
    return r;
}

__device__ __forceinline__ void cp16(void* smem_dst, const void* gsrc) {
    unsigned s = (unsigned)__cvta_generic_to_shared(smem_dst);
    asm volatile("cp.async.cg.shared.global [%0], [%1], 16;\n"
                 :: "r"(s), "l"(gsrc));
}
#define CP_COMMIT() asm volatile("cp.async.commit_group;\n" ::: "memory")
#define CP_WAIT1()  asm volatile("cp.async.wait_group 1;\n" ::: "memory")

__device__ __forceinline__ void stage_tile(float* dst, const float* __restrict__ qf,
                                           int tile, int tid) {
    const float4* src = (const float4*)(qf + (size_t)tile * (TILE_Q * DIM));
    float4* d4 = (float4*)dst;
#pragma unroll
    for (int k = 0; k < 4; k++)                      // 1024 float4 per tile
        cp16(&d4[k * TPB + tid], &src[k * TPB + tid]);
}

// ---------------- init: support sums + initial centroids + dtype detect -----
__global__ void init_kernel(const float* __restrict__ sup, const void* slab) {
    __shared__ int s64;
    if (threadIdx.x == 0) {
        // support_labels = arange(512) % 16. If stored as int32, the int64
        // view of words 1..3 has nonzero high halves; if int64, all zero.
        const unsigned long long* p = (const unsigned long long*)slab;
        int is64 = 1;
#pragma unroll
        for (int i = 0; i < 4; i++)
            if ((p[i] >> 32) != 0ull) is64 = 0;
        s64 = is64;
        g_lab64 = is64;
        g_match = 0;
    }
    __syncthreads();
    const int is64 = s64;
    const int c = threadIdx.x >> 5;      // warp == class (512 threads)
    const int j = threadIdx.x & 31;      // dim pair
    const long long* l64 = (const long long*)slab;
    const int*       l32 = (const int*)slab;

    float sx = 0.f, sy = 0.f;
    int cnt = 0;
    for (int s = 0; s < NSUP; s++) {
        int lbl = is64 ? (int)l64[s] : l32[s];
        if (lbl == c) {
            float2 v = ((const float2*)(sup + s * DIM))[j];
            sx += v.x; sy += v.y; cnt++;
        }
    }
    g_sup_sum[c][2 * j]     = sx;
    g_sup_sum[c][2 * j + 1] = sy;
    float inv = 1.0f / (float)cnt;
    float c0 = sx * inv, c1 = sy * inv;
    g_cs[c][2 * j]     = 2.0f * BETA_F * c0;
    g_cs[c][2 * j + 1] = 2.0f * BETA_F * c1;
    float sq = c0 * c0 + c1 * c1;
#pragma unroll
    for (int m = 16; m > 0; m >>= 1)
        sq += __shfl_xor_sync(0xffffffffu, sq, m);
    if (j == 0) {
        g_counts[c] = (float)cnt;
        g_bias[c]   = BETA_F * sq;
    }
}

// ---------------- fused iteration kernel ------------------------------------
__global__ void __launch_bounds__(TPB, 2)
iter_kernel(const float* __restrict__ qf) {
    __shared__ alignas(16) float sbuf[2][TILE_Q * DIM];  // 2 x 16 KB
    __shared__ float2 sacc[32][17];                      // padded vs conflicts
    __shared__ float  sden[32];

    const int tid  = threadIdx.x;
    const int wid  = tid >> 5;
    const int lane = tid & 31;
    const int c    = lane & 15;
    const int h    = lane >> 4;

    // class parameters (2*beta*c), chunks {2k+h} of the class row
    float4 cs[8];
    const float4* csrow = (const float4*)g_cs[c];
#pragma unroll
    for (int k = 0; k < 8; k++) cs[k] = csrow[2 * k + h];
    const float bias = g_bias[c];

    float2 acc[16];
#pragma unroll
    for (int i = 0; i < 16; i++) { acc[i].x = 0.f; acc[i].y = 0.f; }
    float wsum = 0.f;

    int t = blockIdx.x;
    if (t < NTILES) stage_tile(sbuf[0], qf, t, tid);
    CP_COMMIT();
    int buf = 0;

    for (; t < NTILES; t += gridDim.x) {
        int tn = t + gridDim.x;
        if (tn < NTILES) stage_tile(sbuf[buf ^ 1], qf, tn, tid);
        CP_COMMIT();
        CP_WAIT1();
        __syncthreads();

        const float* base = sbuf[buf] + wid * (QPW * DIM);

        // ---- phase 1: 8 independent dot products -> logits ----
        float logit[QPW];
#pragma unroll
        for (int qi = 0; qi < QPW; qi++) {
            const float4* qrow = (const float4*)(base + qi * DIM);
            float2 dA = {0.f, 0.f}, dB = {0.f, 0.f};
#pragma unroll
            for (int k = 0; k < 8; k++) {
                float4 qv = qrow[2 * k + h];
                float2 q01 = {qv.x, qv.y}, q23 = {qv.z, qv.w};
                float2 c01 = {cs[k].x, cs[k].y}, c23 = {cs[k].z, cs[k].w};
                dA = ffma2(q01, c01, dA);
                dB = ffma2(q23, c23, dB);
            }
            float dot = (dA.x + dA.y) + (dB.x + dB.y);
            dot += __shfl_xor_sync(0xffffffffu, dot, 16);  // combine halves
            logit[qi] = dot - bias;                        // beta*(2qc-|c|^2)
        }

        // ---- phase 2: 8 softmaxes, butterfly chains interleaved 8-wide ----
        float m[QPW];
#pragma unroll
        for (int qi = 0; qi < QPW; qi++) m[qi] = logit[qi];
#pragma unroll
        for (int msk = 8; msk >= 1; msk >>= 1) {
#pragma unroll
            for (int qi = 0; qi < QPW; qi++)
                m[qi] = fmaxf(m[qi], __shfl_xor_sync(0xffffffffu, m[qi], msk));
        }
        float e[QPW], s[QPW];
#pragma unroll
        for (int qi = 0; qi < QPW; qi++) {
            e[qi] = __expf(logit[qi] - m[qi]);
            s[qi] = e[qi];
        }
#pragma unroll
        for (int msk = 8; msk >= 1; msk >>= 1) {
#pragma unroll
            for (int qi = 0; qi < QPW; qi++)
                s[qi] += __shfl_xor_sync(0xffffffffu, s[qi], msk);
        }
        float wv[QPW];
#pragma unroll
        for (int qi = 0; qi < QPW; qi++) {
            wv[qi] = __fdividef(e[qi], s[qi]);
            wsum += wv[qi];
        }

        // ---- phase 3: weighted accumulation (reload q from smem) ----
        __syncwarp();   // memory barrier: force reload instead of 64-float4 liveness
#pragma unroll
        for (int qi = 0; qi < QPW; qi++) {
            const float4* qrow = (const float4*)(base + qi * DIM);
            float2 wp = {wv[qi], wv[qi]};
#pragma unroll
            for (int k = 0; k < 8; k++) {
                float4 qv = qrow[2 * k + h];
                float2 q01 = {qv.x, qv.y}, q23 = {qv.z, qv.w};
                acc[2 * k]     = ffma2(wp, q01, acc[2 * k]);
                acc[2 * k + 1] = ffma2(wp, q23, acc[2 * k + 1]);
            }
        }

        buf ^= 1;
        __syncthreads();
    }

    // deterministic block flush: serialize warps into smem, then write partials
    for (int ws = 0; ws < NWARPS; ws++) {
        if (wid == ws) {
            if (ws == 0) {
#pragma unroll
                for (int i = 0; i < 16; i++) sacc[lane][i] = acc[i];
                sden[lane] = wsum;
            } else {
#pragma unroll
                for (int i = 0; i < 16; i++) {
                    sacc[lane][i].x += acc[i].x;
                    sacc[lane][i].y += acc[i].y;
                }
                sden[lane] += wsum;
            }
        }
        __syncthreads();
    }
    if (wid == 0) {
#pragma unroll
        for (int i = 0; i < 16; i++)
            g_part[blockIdx.x][lane][i] = sacc[lane][i];
    }
    if (wid == 1 && lane < 16)
        g_pden[blockIdx.x][lane] = sden[lane];   // both halves equal; h=0 copy
}

// ---------------- centroid update (16 blocks, deterministic) ----------------
__global__ void reduce_kernel() {
    __shared__ float2 red[8][32];
    __shared__ float  dch[8];
    __shared__ float  sqv[32];
    __shared__ float  den_s;

    const int c     = blockIdx.x;       // class
    const int tid   = threadIdx.x;      // 256 threads
    const int s     = tid & 31;         // slot: h = s>>4, i = s&15
    const int chunk = tid >> 5;         // 8 chunks over GRID_MAIN blocks
    const int hh    = s >> 4;
    const int ii    = s & 15;
    const int l     = c + 16 * hh;
    const int per   = GRID_MAIN / 8;    // 37

    float2 t2 = {0.f, 0.f};
    float dsum = 0.f;
    const int b0 = chunk * per;
    for (int b = b0; b < b0 + per; b++) {
        float2 v = g_part[b][l][ii];
        t2.x += v.x; t2.y += v.y;
        if (s == 0) dsum += g_pden[b][c];
    }
    red[chunk][s] = t2;
    if (s == 0) dch[chunk] = dsum;
    __syncthreads();

    if (tid == 0) {
        float dtot = g_counts[c];
        for (int k = 0; k < 8; k++) dtot += dch[k];
        den_s = dtot;
    }
    __syncthreads();

    if (tid < 32) {
        float2 tot = red[0][tid];
#pragma unroll
        for (int k = 1; k < 8; k++) {
            tot.x += red[k][tid].x;
            tot.y += red[k][tid].y;
        }
        const int h2 = tid >> 4, i2 = tid & 15;
        const int k2 = i2 >> 1, r2 = i2 & 1;
        const int d0 = 8 * k2 + 4 * h2 + 2 * r2;   // matches iter acc layout
        float num0 = g_sup_sum[c][d0]     + tot.x;
        float num1 = g_sup_sum[c][d0 + 1] + tot.y;
        float c0 = num0 / den_s;
        float c1 = num1 / den_s;
        g_cs[c][d0]     = 2.0f * BETA_F * c0;
        g_cs[c][d0 + 1] = 2.0f * BETA_F * c1;
        sqv[tid] = c0 * c0 + c1 * c1;
    }
    __syncthreads();
    if (tid == 0) {
        float sq = 0.f;
        for (int k = 0; k < 32; k++) sq += sqv[k];
        g_bias[c] = BETA_F * sq;
    }
}

// ---------------- final prediction + accuracy count -------------------------
__global__ void __launch_bounds__(TPB, 2)
predict_kernel(const float* __restrict__ qf, const void* __restrict__ qlab) {
    __shared__ alignas(16) float sbuf[2][TILE_Q * DIM];
    __shared__ int scnt[NWARPS];

    const int tid  = threadIdx.x;
    const int wid  = tid >> 5;
    const int lane = tid & 31;
    const int c    = lane & 15;
    const int h    = lane >> 4;

    float4 cs[8];
    const float4* csrow = (const float4*)g_cs[c];
#pragma unroll
    for (int k = 0; k < 8; k++) cs[k] = csrow[2 * k + h];
    const float bias = g_bias[c];

    const int is64 = g_lab64;
    const long long* L64 = (const long long*)qlab;
    const int*       L32 = (const int*)qlab;

    int cnt = 0;
    int t = blockIdx.x;
    if (t < NTILES) stage_tile(sbuf[0], qf, t, tid);
    CP_COMMIT();
    int buf = 0;

    for (; t < NTILES; t += gridDim.x) {
        int tn = t + gridDim.x;
        if (tn < NTILES) stage_tile(sbuf[buf ^ 1], qf, tn, tid);
        CP_COMMIT();
        CP_WAIT1();
        __syncthreads();

        const float* base = sbuf[buf] + wid * (QPW * DIM);

        // phase 1: 8 dots
        float v[QPW];
#pragma unroll
        for (int qi = 0; qi < QPW; qi++) {
            const float4* qrow = (const float4*)(base + qi * DIM);
            float2 dA = {0.f, 0.f}, dB = {0.f, 0.f};
#pragma unroll
            for (int k = 0; k < 8; k++) {
                float4 qv = qrow[2 * k + h];
                float2 q01 = {qv.x, qv.y}, q23 = {qv.z, qv.w};
                float2 c01 = {cs[k].x, cs[k].y}, c23 = {cs[k].z, cs[k].w};
                dA = ffma2(q01, c01, dA);
                dB = ffma2(q23, c23, dB);
            }
            float dot = (dA.x + dA.y) + (dB.x + dB.y);
            dot += __shfl_xor_sync(0xffffffffu, dot, 16);
            v[qi] = dot - bias;            // argmax v == argmin d2
        }

        // phase 2: 8 interleaved argmax butterflies
        int bi[QPW];
#pragma unroll
        for (int qi = 0; qi < QPW; qi++) bi[qi] = c;
#pragma unroll
        for (int msk = 8; msk >= 1; msk >>= 1) {
#pragma unroll
            for (int qi = 0; qi < QPW; qi++) {
                float ov = __shfl_xor_sync(0xffffffffu, v[qi], msk);
                int   oi = __shfl_xor_sync(0xffffffffu, bi[qi], msk);
                if (ov > v[qi] || (ov == v[qi] && oi < bi[qi])) {
                    v[qi] = ov; bi[qi] = oi;
                }
            }
        }
        if (lane == 0) {
#pragma unroll
            for (int qi = 0; qi < QPW; qi++) {
                int qg = t * TILE_Q + wid * QPW + qi;
                int lbl = is64 ? (int)L64[qg] : L32[qg];
                if (bi[qi] == lbl) cnt++;
            }
        }
        buf ^= 1;
        __syncthreads();
    }

    if (lane == 0) scnt[wid] = cnt;
    __syncthreads();
    if (tid == 0) {
        int bc = 0;
#pragma unroll
        for (int w = 0; w < NWARPS; w++) bc += scnt[w];
        atomicAdd(&g_match, bc);           // integer atomic: deterministic
    }
}

__global__ void finalize_kernel(float* out) {
    out[0] = (float)g_match / (float)NQ;
}

// ---------------- launch ----------------------------------------------------
extern "C" void kernel_launch(void* const* d_in, const int* in_sizes, int n_in,
                              void* d_out, int out_size) {
    (void)in_sizes; (void)n_in; (void)out_size;
    const float* sup  = (const float*)d_in[0];
    const float* qf   = (const float*)d_in[1];
    const void*  slab = d_in[2];
    const void*  qlab = d_in[3];
    float* out = (float*)d_out;

    init_kernel<<<1, 512>>>(sup, slab);
    for (int it = 0; it < NITER; ++it) {
        iter_kernel<<<GRID_MAIN, TPB>>>(qf);
        reduce_kernel<<<NCLS, 256>>>();
    }
    predict_kernel<<<GRID_MAIN, TPB>>>(qf, qlab);
    finalize_kernel<<<1, 1>>>(out);
}